// round 16
// baseline (speedup 1.0000x reference)
#include <cuda_runtime.h>
#include <cstdint>

#define BB 8
#define SS 1024
#define DD 1024
#define HH 16
#define DHD 64   // head dim

// Scratch (tf32-rounded, octet-permuted cols: slot(w)=2*(w&3)+(w>>2) per 8-col octet):
// g_q [bh][s][64] (pre-scaled by 0.125*log2e), g_k [bh][s][64], g_vT [bh][64][s]
__device__ float g_q[BB * HH * SS * DHD];
__device__ float g_k[BB * HH * SS * DHD];
__device__ float g_vT[BB * HH * DHD * SS];

// ---------------- helpers ----------------
__device__ __forceinline__ float tf32rn(float x) {
    uint32_t u;
    asm("cvt.rn.tf32.f32 %0, %1;" : "=r"(u) : "f"(x));
    return __uint_as_float(u);
}
__device__ __forceinline__ float ex2f(float x) {
    float r;
    asm("ex2.approx.ftz.f32 %0, %1;" : "=f"(r) : "f"(x));
    return r;
}
__device__ __forceinline__ uint32_t smem_to_u32(const void* p) {
    uint32_t a;
    asm("{ .reg .u64 t; cvta.to.shared.u64 t, %1; cvt.u32.u64 %0, t; }"
        : "=r"(a) : "l"(p));
    return a;
}
__device__ __forceinline__ void cp16(uint32_t dst, const void* src) {
    asm volatile("cp.async.cg.shared.global [%0], [%1], 16;"
                 :: "r"(dst), "l"(src) : "memory");
}
#define CP_COMMIT() asm volatile("cp.async.commit_group;" ::: "memory")
#define CP_WAIT_ALL() asm volatile("cp.async.wait_group 0;" ::: "memory")

#define MMA_TF32(c, a, b0, b1) \
    asm volatile("mma.sync.aligned.m16n8k8.row.col.f32.tf32.tf32.f32 " \
        "{%0,%1,%2,%3}, {%4,%5,%6,%7}, {%8,%9}, {%0,%1,%2,%3};" \
        : "+f"((c)[0]), "+f"((c)[1]), "+f"((c)[2]), "+f"((c)[3]) \
        : "r"((a)[0]), "r"((a)[1]), "r"((a)[2]), "r"((a)[3]), \
          "r"(b0), "r"(b1))

// octet-permute a row-chunk float4 using the lane^xorbit partner.
__device__ __forceinline__ float4 perm_shfl(float4 f, int xorbit, bool odd) {
    float4 p;
    p.x = __shfl_xor_sync(0xffffffffu, f.x, xorbit);
    p.y = __shfl_xor_sync(0xffffffffu, f.y, xorbit);
    p.z = __shfl_xor_sync(0xffffffffu, f.z, xorbit);
    p.w = __shfl_xor_sync(0xffffffffu, f.w, xorbit);
    return odd ? make_float4(p.z, f.z, p.w, f.w)
               : make_float4(f.x, p.x, f.y, p.y);
}

#define QSCALE 0.18033688011112042f   // 0.125 * log2(e)

// =====================================================================
// Kernel 1: QKV projection on mma.sync tf32 — direct-STG epilogues.
// grid (128 tiles, 16 heads), 128 threads (4 warps 2m x 2n).
// q and k are stored straight from C-fragments with STG.32 into the
// octet-permuted layout (per row-group/octet the warp covers a full
// 32B sector). Only vT stages through smem (transpose). 2 barriers.
// =====================================================================
#define QSPW 72
#define XSo  0
#define WQo  4608         // 64*72
#define WKo  9216
#define WVo  13824
#define OUTo 18432
#define QKV_SMEM ((18432 + 4608) * 4)   // 92160 B

#define QKV_GEMM(acc, Woff) do { \
    _Pragma("unroll") \
    for (int m_ = 0; m_ < 2; m_++) \
        _Pragma("unroll") \
        for (int t_ = 0; t_ < 4; t_++) \
            _Pragma("unroll") \
            for (int q_ = 0; q_ < 4; q_++) (acc)[m_][t_][q_] = 0.f; \
    _Pragma("unroll") \
    for (int t_ = 0; t_ < 4; t_++) { \
        const float* bp_ = smf + (Woff) + (wn * 32 + t_ * 8 + g) * QSPW + 2 * c; \
        _Pragma("unroll") \
        for (int s_ = 0; s_ < 8; s_++) { \
            float2 b2_ = *(const float2*)(bp_ + s_ * 8); \
            uint32_t b0_ = __float_as_uint(b2_.x), b1_ = __float_as_uint(b2_.y); \
            MMA_TF32((acc)[0][t_], qa[0][s_], b0_, b1_); \
            MMA_TF32((acc)[1][t_], qa[1][s_], b0_, b1_); \
        } \
    } \
} while (0)

__global__ void __launch_bounds__(128) qkv_kernel(
    const float* __restrict__ x,
    const float* __restrict__ Wq, const float* __restrict__ bq,
    const float* __restrict__ Wk, const float* __restrict__ bk,
    const float* __restrict__ Wv, const float* __restrict__ bv)
{
    extern __shared__ float smf[];
    const int tid  = threadIdx.x;
    const int wid  = tid >> 5;
    const int lane = tid & 31;
    const int g    = lane >> 2;
    const int c    = lane & 3;
    const int wm   = wid >> 1;
    const int wn   = wid & 1;

    const int tile = blockIdx.x;     // 0..127
    const int h    = blockIdx.y;     // 0..15
    const int t0   = tile * 64;
    const int prow = tid >> 4;       // 0..7
    const int pch  = tid & 15;       // float4 chunk
    const bool odd = pch & 1;

    // ---- load X and W tiles, octet-permuted along k ----
#pragma unroll
    for (int p = 0; p < 8; p++) {
        int row = prow + p * 8;
        float4 xv = *(const float4*)(x + (size_t)(t0 + row) * DD + h * DHD + pch * 4);
        *(float4*)&smf[XSo + row * QSPW + pch * 4] = perm_shfl(xv, 1, odd);
        size_t wb = ((size_t)h * DHD + row) * DHD + pch * 4;
        *(float4*)&smf[WQo + row * QSPW + pch * 4] =
            perm_shfl(*(const float4*)(Wq + wb), 1, odd);
        *(float4*)&smf[WKo + row * QSPW + pch * 4] =
            perm_shfl(*(const float4*)(Wk + wb), 1, odd);
        *(float4*)&smf[WVo + row * QSPW + pch * 4] =
            perm_shfl(*(const float4*)(Wv + wb), 1, odd);
    }
    __syncthreads();   // B1

    // ---- A fragments from X (persistent for all 3 GEMMs) ----
    uint32_t qa[2][8][4];
#pragma unroll
    for (int m = 0; m < 2; m++) {
        int r = wm * 32 + m * 16 + g;
#pragma unroll
        for (int s = 0; s < 8; s++) {
            float2 lo = *(const float2*)&smf[XSo + r * QSPW + s * 8 + 2 * c];
            float2 hi = *(const float2*)&smf[XSo + (r + 8) * QSPW + s * 8 + 2 * c];
            qa[m][s][0] = __float_as_uint(lo.x);
            qa[m][s][1] = __float_as_uint(hi.x);
            qa[m][s][2] = __float_as_uint(lo.y);
            qa[m][s][3] = __float_as_uint(hi.y);
        }
    }

    const int sl0 = ((c & 1) << 2) | (c >> 1);       // slot(2c); slot(2c+1)=sl0+2
    const int slg = 2 * (g & 3) + (g >> 2);          // slot(g)
    const int bh  = (t0 >> 10) * HH + h;
    const int s0  = (t0 & 1023);

    // ---- GEMM q -> direct STG (bias+scale+tf32, permuted layout) ----
    {
        float acc[2][4][4];
        QKV_GEMM(acc, WQo);
        float b0r[4], b1r[4];
#pragma unroll
        for (int t = 0; t < 4; t++) {
            int e = wn * 32 + t * 8 + 2 * c;
            b0r[t] = bq[h * DHD + e];
            b1r[t] = bq[h * DHD + e + 1];
        }
#pragma unroll
        for (int m = 0; m < 2; m++) {
            int r = wm * 32 + m * 16 + g;
            float* q0 = &g_q[((size_t)bh * SS + s0 + r) * DHD + wn * 32];
            float* q1 = &g_q[((size_t)bh * SS + s0 + r + 8) * DHD + wn * 32];
#pragma unroll
            for (int t = 0; t < 4; t++) {
                q0[t * 8 + sl0]     = tf32rn((acc[m][t][0] + b0r[t]) * QSCALE);
                q0[t * 8 + sl0 + 2] = tf32rn((acc[m][t][1] + b1r[t]) * QSCALE);
                q1[t * 8 + sl0]     = tf32rn((acc[m][t][2] + b0r[t]) * QSCALE);
                q1[t * 8 + sl0 + 2] = tf32rn((acc[m][t][3] + b1r[t]) * QSCALE);
            }
        }
    }

    // ---- GEMM k -> direct STG ----
    {
        float acc[2][4][4];
        QKV_GEMM(acc, WKo);
        float b0r[4], b1r[4];
#pragma unroll
        for (int t = 0; t < 4; t++) {
            int e = wn * 32 + t * 8 + 2 * c;
            b0r[t] = bk[h * DHD + e];
            b1r[t] = bk[h * DHD + e + 1];
        }
#pragma unroll
        for (int m = 0; m < 2; m++) {
            int r = wm * 32 + m * 16 + g;
            float* k0 = &g_k[((size_t)bh * SS + s0 + r) * DHD + wn * 32];
            float* k1 = &g_k[((size_t)bh * SS + s0 + r + 8) * DHD + wn * 32];
#pragma unroll
            for (int t = 0; t < 4; t++) {
                k0[t * 8 + sl0]     = tf32rn(acc[m][t][0] + b0r[t]);
                k0[t * 8 + sl0 + 2] = tf32rn(acc[m][t][1] + b1r[t]);
                k1[t * 8 + sl0]     = tf32rn(acc[m][t][2] + b0r[t]);
                k1[t * 8 + sl0 + 2] = tf32rn(acc[m][t][3] + b1r[t]);
            }
        }
    }

    // ---- GEMM v -> stage transposed in OUT -> STG ----
    {
        float acc[2][4][4];
        QKV_GEMM(acc, WVo);
        float b0r[4], b1r[4];
#pragma unroll
        for (int t = 0; t < 4; t++) {
            int e = wn * 32 + t * 8 + 2 * c;
            b0r[t] = bv[h * DHD + e];
            b1r[t] = bv[h * DHD + e + 1];
        }
#pragma unroll
        for (int m = 0; m < 2; m++) {
            int r    = wm * 32 + m * 16 + g;
            int ptk0 = r - g + slg;        // permuted token slot (row r)
            int ptk1 = ptk0 + 8;           // row r+8 (next octet, same slot)
#pragma unroll
            for (int t = 0; t < 4; t++) {
                int e = wn * 32 + t * 8 + 2 * c;
                smf[OUTo + e * QSPW + ptk0]       = tf32rn(acc[m][t][0] + b0r[t]);
                smf[OUTo + (e + 1) * QSPW + ptk0] = tf32rn(acc[m][t][1] + b1r[t]);
                smf[OUTo + e * QSPW + ptk1]       = tf32rn(acc[m][t][2] + b0r[t]);
                smf[OUTo + (e + 1) * QSPW + ptk1] = tf32rn(acc[m][t][3] + b1r[t]);
            }
        }
    }
    __syncthreads();   // B2: v staged

    // STG vT: rows are e, columns are (permuted) tokens WITHIN the batch (s0)
#pragma unroll
    for (int p = 0; p < 8; p++) {
        int erow = prow + p * 8;
        *(float4*)&g_vT[((size_t)bh * DHD + erow) * SS + s0 + pch * 4] =
            *(const float4*)&smf[OUTo + erow * QSPW + pch * 4];
    }
}

// =====================================================================
// Kernel 2: tf32 mma.sync flash attention (byte-identical to R12 pass).
// =====================================================================
#define SPW 72
#define KF  0
#define V0F 4608
#define V1F 9216
#define PF  13824
#define LRF 18432
#define ATTN_SMEM ((18432 + 128) * 4)   // 74240 B

__global__ void __launch_bounds__(128, 3) attn_kernel(float* __restrict__ out)
{
    extern __shared__ float smf[];
    const uint32_t smb = smem_to_u32(smf);
    const int tid  = threadIdx.x;
    const int wid  = tid >> 5;
    const int lane = tid & 31;
    const int g    = lane >> 2;
    const int c    = lane & 3;
    const int wm   = wid >> 1;
    const int wn   = wid & 1;

    const int qt = blockIdx.x;
    const int bh = blockIdx.y;
    const int b  = bh >> 4, h = bh & 15;
    const int m0 = qt * 64;

    const float* qbase = g_q + (size_t)bh * SS * DHD;
    const float* kbase = g_k + (size_t)bh * SS * DHD;
    const float* vTb   = g_vT + (size_t)bh * DHD * SS;

    float* Psm  = smf + PF;
    float* lred = smf + LRF;

    const int prow = tid >> 4;
    const int pch  = tid & 15;
    const uint32_t kdst  = smb + (KF  + prow * SPW + pch * 4) * 4;
    const uint32_t v0dst = smb + (V0F + prow * SPW + pch * 4) * 4;
    const uint32_t v1dst = smb + (V1F + prow * SPW + pch * 4) * 4;
    const float* kgs = kbase + (size_t)prow * DHD + pch * 4;
    const float* vgs = vTb + (size_t)prow * SS + pch * 4;

#pragma unroll
    for (int p = 0; p < 8; p++) {
        cp16(kdst + p * (8 * SPW * 4), kgs + (size_t)p * 8 * DHD);
        cp16(v0dst + p * (8 * SPW * 4), vgs + (size_t)p * 8 * SS);
    }
    CP_COMMIT();

#pragma unroll
    for (int it = 0; it < 8; it++) {
        int idx = tid + it * 128;
        int row = idx >> 4;
        int ch  = idx & 15;
        *(float4*)&Psm[row * SPW + ch * 4] =
            *(const float4*)(qbase + (size_t)(m0 + row) * DHD + ch * 4);
    }
    __syncthreads();

    uint32_t qa[2][8][4];
#pragma unroll
    for (int m = 0; m < 2; m++) {
        int r = wm * 32 + m * 16 + g;
#pragma unroll
        for (int s = 0; s < 8; s++) {
            float2 lo = *(const float2*)&Psm[r * SPW + s * 8 + 2 * c];
            float2 hi = *(const float2*)&Psm[(r + 8) * SPW + s * 8 + 2 * c];
            qa[m][s][0] = __float_as_uint(lo.x);
            qa[m][s][1] = __float_as_uint(hi.x);
            qa[m][s][2] = __float_as_uint(lo.y);
            qa[m][s][3] = __float_as_uint(hi.y);
        }
    }

    float oacc[2][4][4];
#pragma unroll
    for (int m = 0; m < 2; m++)
#pragma unroll
        for (int t = 0; t < 4; t++)
#pragma unroll
            for (int q = 0; q < 4; q++) oacc[m][t][q] = 0.f;
    float lacc[2][2] = {{0.f, 0.f}, {0.f, 0.f}};

    const int sl0 = ((c & 1) << 2) | (c >> 1);

    for (int kt = 0; kt < 16; kt++) {
        CP_WAIT_ALL();
        __syncthreads();

        if (kt < 15) {
            uint32_t vd = (kt & 1) ? v0dst : v1dst;
            const float* vsrc = vgs + (size_t)(kt + 1) * 64;
#pragma unroll
            for (int p = 0; p < 8; p++)
                cp16(vd + p * (8 * SPW * 4), vsrc + (size_t)p * 8 * SS);
            CP_COMMIT();
        }

        const float* Kb = smf + KF;
        float sacc[2][4][4];
#pragma unroll
        for (int m = 0; m < 2; m++)
#pragma unroll
            for (int t = 0; t < 4; t++)
#pragma unroll
                for (int q = 0; q < 4; q++) sacc[m][t][q] = 0.f;
#pragma unroll
        for (int t = 0; t < 4; t++) {
            const float* bp = Kb + (wn * 32 + t * 8 + g) * SPW + 2 * c;
#pragma unroll
            for (int s = 0; s < 8; s++) {
                float2 b2 = *(const float2*)(bp + s * 8);
                uint32_t b0 = __float_as_uint(b2.x), b1 = __float_as_uint(b2.y);
                MMA_TF32(sacc[0][t], qa[0][s], b0, b1);
                MMA_TF32(sacc[1][t], qa[1][s], b0, b1);
            }
        }

#pragma unroll
        for (int m = 0; m < 2; m++) {
            int r = wm * 32 + m * 16 + g;
            float* p0 = Psm + r * SPW + wn * 32;
            float* p1 = Psm + (r + 8) * SPW + wn * 32;
#pragma unroll
            for (int t = 0; t < 4; t++) {
                float e0 = tf32rn(ex2f(sacc[m][t][0]));
                float e1 = tf32rn(ex2f(sacc[m][t][1]));
                float e2 = tf32rn(ex2f(sacc[m][t][2]));
                float e3 = tf32rn(ex2f(sacc[m][t][3]));
                lacc[m][0] += e0 + e1;
                lacc[m][1] += e2 + e3;
                p0[t * 8 + sl0]     = e0;
                p0[t * 8 + sl0 + 2] = e1;
                p1[t * 8 + sl0]     = e2;
                p1[t * 8 + sl0 + 2] = e3;
            }
        }
        __syncthreads();

        if (kt < 15) {
            const float* ksrc = kgs + (size_t)(kt + 1) * 64 * DHD;
#pragma unroll
            for (int p = 0; p < 8; p++)
                cp16(kdst + p * (8 * SPW * 4), ksrc + (size_t)p * 8 * DHD);
            CP_COMMIT();
        }

        const float* Vb = smf + ((kt & 1) ? V1F : V0F);
#pragma unroll
        for (int s = 0; s < 8; s++) {
            uint32_t pa[2][4];
#pragma unroll
            for (int m = 0; m < 2; m++) {
                int r = wm * 32 + m * 16 + g;
                float2 a0 = *(const float2*)(Psm + r * SPW + s * 8 + 2 * c);
                float2 a1 = *(const float2*)(Psm + (r + 8) * SPW + s * 8 + 2 * c);
                pa[m][0] = __float_as_uint(a0.x);
                pa[m][1] = __float_as_uint(a1.x);
                pa[m][2] = __float_as_uint(a0.y);
                pa[m][3] = __float_as_uint(a1.y);
            }
#pragma unroll
            for (int t = 0; t < 4; t++) {
                float2 b2 = *(const float2*)(Vb + (wn * 32 + t * 8 + g) * SPW + s * 8 + 2 * c);
                uint32_t b0 = __float_as_uint(b2.x), b1 = __float_as_uint(b2.y);
                MMA_TF32(oacc[0][t], pa[0], b0, b1);
                MMA_TF32(oacc[1][t], pa[1], b0, b1);
            }
        }
    }

#pragma unroll
    for (int m = 0; m < 2; m++)
#pragma unroll
        for (int hh = 0; hh < 2; hh++) {
            lacc[m][hh] += __shfl_xor_sync(0xffffffffu, lacc[m][hh], 1);
            lacc[m][hh] += __shfl_xor_sync(0xffffffffu, lacc[m][hh], 2);
        }
    if (c == 0) {
#pragma unroll
        for (int m = 0; m < 2; m++) {
            int r = wm * 32 + m * 16 + g;
            lred[r * 2 + wn]       = lacc[m][0];
            lred[(r + 8) * 2 + wn] = lacc[m][1];
        }
    }
    __syncthreads();

#pragma unroll
    for (int m = 0; m < 2; m++) {
        int r = wm * 32 + m * 16 + g;
        float inv0 = 1.f / (lred[r * 2] + lred[r * 2 + 1]);
        float inv1 = 1.f / (lred[(r + 8) * 2] + lred[(r + 8) * 2 + 1]);
        size_t o0 = (((size_t)b * SS + m0 + r) * HH + h) * DHD;
        size_t o1 = (((size_t)b * SS + m0 + r + 8) * HH + h) * DHD;
#pragma unroll
        for (int t = 0; t < 4; t++) {
            int col = wn * 32 + t * 8 + 2 * c;
            *(float2*)&out[o0 + col] =
                make_float2(oacc[m][t][0] * inv0, oacc[m][t][1] * inv0);
            *(float2*)&out[o1 + col] =
                make_float2(oacc[m][t][2] * inv1, oacc[m][t][3] * inv1);
        }
    }
}

// =====================================================================
extern "C" void kernel_launch(void* const* d_in, const int* in_sizes, int n_in,
                              void* d_out, int out_size)
{
    const float* x  = (const float*)d_in[0];
    const float* Wq = (const float*)d_in[1];
    const float* bq = (const float*)d_in[2];
    const float* Wk = (const float*)d_in[3];
    const float* bk = (const float*)d_in[4];
    const float* Wv = (const float*)d_in[5];
    const float* bv = (const float*)d_in[6];
    float* out = (float*)d_out;

    static bool attr_set = false;
    if (!attr_set) {
        cudaFuncSetAttribute(qkv_kernel,
                             cudaFuncAttributeMaxDynamicSharedMemorySize, QKV_SMEM);
        cudaFuncSetAttribute(attn_kernel,
                             cudaFuncAttributeMaxDynamicSharedMemorySize, ATTN_SMEM);
        attr_set = true;
    }

    qkv_kernel<<<dim3(128, 16), 128, QKV_SMEM>>>(x, Wq, bq, Wk, bk, Wv, bv);
    attn_kernel<<<dim3(16, 128), 128, ATTN_SMEM>>>(out);
}

// round 17
// speedup vs baseline: 1.5800x; 1.5800x over previous
#include <cuda_runtime.h>
#include <cstdint>

#define BB 8
#define SS 1024
#define DD 1024
#define HH 16
#define DHD 64   // head dim

// Scratch (tf32-rounded, octet-permuted cols: slot(w)=2*(w&3)+(w>>2) per 8-col octet):
// g_q [bh][s][64] (pre-scaled by 0.125*log2e), g_k [bh][s][64], g_vT [bh][64][s]
__device__ float g_q[BB * HH * SS * DHD];
__device__ float g_k[BB * HH * SS * DHD];
__device__ float g_vT[BB * HH * DHD * SS];

// ---------------- helpers ----------------
__device__ __forceinline__ float tf32rn(float x) {
    uint32_t u;
    asm("cvt.rn.tf32.f32 %0, %1;" : "=r"(u) : "f"(x));
    return __uint_as_float(u);
}
__device__ __forceinline__ float ex2f(float x) {
    float r;
    asm("ex2.approx.ftz.f32 %0, %1;" : "=f"(r) : "f"(x));
    return r;
}
__device__ __forceinline__ uint32_t smem_to_u32(const void* p) {
    uint32_t a;
    asm("{ .reg .u64 t; cvta.to.shared.u64 t, %1; cvt.u32.u64 %0, t; }"
        : "=r"(a) : "l"(p));
    return a;
}
__device__ __forceinline__ void cp16(uint32_t dst, const void* src) {
    asm volatile("cp.async.cg.shared.global [%0], [%1], 16;"
                 :: "r"(dst), "l"(src) : "memory");
}
#define CP_COMMIT() asm volatile("cp.async.commit_group;" ::: "memory")
#define CP_WAIT_ALL() asm volatile("cp.async.wait_group 0;" ::: "memory")

#define MMA_TF32(c, a, b0, b1) \
    asm volatile("mma.sync.aligned.m16n8k8.row.col.f32.tf32.tf32.f32 " \
        "{%0,%1,%2,%3}, {%4,%5,%6,%7}, {%8,%9}, {%0,%1,%2,%3};" \
        : "+f"((c)[0]), "+f"((c)[1]), "+f"((c)[2]), "+f"((c)[3]) \
        : "r"((a)[0]), "r"((a)[1]), "r"((a)[2]), "r"((a)[3]), \
          "r"(b0), "r"(b1))

// octet-permute a row-chunk float4 using the lane^xorbit partner.
__device__ __forceinline__ float4 perm_shfl(float4 f, int xorbit, bool odd) {
    float4 p;
    p.x = __shfl_xor_sync(0xffffffffu, f.x, xorbit);
    p.y = __shfl_xor_sync(0xffffffffu, f.y, xorbit);
    p.z = __shfl_xor_sync(0xffffffffu, f.z, xorbit);
    p.w = __shfl_xor_sync(0xffffffffu, f.w, xorbit);
    return odd ? make_float4(p.z, f.z, p.w, f.w)
               : make_float4(f.x, p.x, f.y, p.y);
}

#define QSCALE 0.18033688011112042f   // 0.125 * log2(e)

// =====================================================================
// Kernel 1: QKV projection on mma.sync tf32 (R12 internals; double-
// buffered OUT staging -> 4 barriers instead of 6, coalesced STG.128).
// grid (128 tiles, 16 heads), 128 threads (4 warps 2m x 2n).
// =====================================================================
#define QSPW 72
#define XSo  0
#define WQo  4608         // 64*72
#define WKo  9216
#define WVo  13824
#define OUTA 18432
#define OUTB 23040
#define QKV_SMEM (27648 * 4)   // 110592 B

#define QKV_GEMM(acc, Woff) do { \
    _Pragma("unroll") \
    for (int m_ = 0; m_ < 2; m_++) \
        _Pragma("unroll") \
        for (int t_ = 0; t_ < 4; t_++) \
            _Pragma("unroll") \
            for (int q_ = 0; q_ < 4; q_++) (acc)[m_][t_][q_] = 0.f; \
    _Pragma("unroll") \
    for (int t_ = 0; t_ < 4; t_++) { \
        const float* bp_ = smf + (Woff) + (wn * 32 + t_ * 8 + g) * QSPW + 2 * c; \
        _Pragma("unroll") \
        for (int s_ = 0; s_ < 8; s_++) { \
            float2 b2_ = *(const float2*)(bp_ + s_ * 8); \
            uint32_t b0_ = __float_as_uint(b2_.x), b1_ = __float_as_uint(b2_.y); \
            MMA_TF32((acc)[0][t_], qa[0][s_], b0_, b1_); \
            MMA_TF32((acc)[1][t_], qa[1][s_], b0_, b1_); \
        } \
    } \
} while (0)

__global__ void __launch_bounds__(128) qkv_kernel(
    const float* __restrict__ x,
    const float* __restrict__ Wq, const float* __restrict__ bq,
    const float* __restrict__ Wk, const float* __restrict__ bk,
    const float* __restrict__ Wv, const float* __restrict__ bv)
{
    extern __shared__ float smf[];
    const int tid  = threadIdx.x;
    const int wid  = tid >> 5;
    const int lane = tid & 31;
    const int g    = lane >> 2;
    const int c    = lane & 3;
    const int wm   = wid >> 1;
    const int wn   = wid & 1;

    const int tile = blockIdx.x;     // 0..127
    const int h    = blockIdx.y;     // 0..15
    const int t0   = tile * 64;
    const int prow = tid >> 4;       // 0..7
    const int pch  = tid & 15;       // float4 chunk
    const bool odd = pch & 1;

    // ---- load X and W tiles, octet-permuted along k ----
#pragma unroll
    for (int p = 0; p < 8; p++) {
        int row = prow + p * 8;
        float4 xv = *(const float4*)(x + (size_t)(t0 + row) * DD + h * DHD + pch * 4);
        *(float4*)&smf[XSo + row * QSPW + pch * 4] = perm_shfl(xv, 1, odd);
        size_t wb = ((size_t)h * DHD + row) * DHD + pch * 4;
        *(float4*)&smf[WQo + row * QSPW + pch * 4] =
            perm_shfl(*(const float4*)(Wq + wb), 1, odd);
        *(float4*)&smf[WKo + row * QSPW + pch * 4] =
            perm_shfl(*(const float4*)(Wk + wb), 1, odd);
        *(float4*)&smf[WVo + row * QSPW + pch * 4] =
            perm_shfl(*(const float4*)(Wv + wb), 1, odd);
    }
    __syncthreads();   // B1

    // ---- A fragments from X (persistent for all 3 GEMMs) ----
    uint32_t qa[2][8][4];
#pragma unroll
    for (int m = 0; m < 2; m++) {
        int r = wm * 32 + m * 16 + g;
#pragma unroll
        for (int s = 0; s < 8; s++) {
            float2 lo = *(const float2*)&smf[XSo + r * QSPW + s * 8 + 2 * c];
            float2 hi = *(const float2*)&smf[XSo + (r + 8) * QSPW + s * 8 + 2 * c];
            qa[m][s][0] = __float_as_uint(lo.x);
            qa[m][s][1] = __float_as_uint(hi.x);
            qa[m][s][2] = __float_as_uint(lo.y);
            qa[m][s][3] = __float_as_uint(hi.y);
        }
    }

    const int sl0 = ((c & 1) << 2) | (c >> 1);       // slot(2c); slot(2c+1)=sl0+2
    const int slg = 2 * (g & 3) + (g >> 2);          // slot(g)
    const int bh  = (t0 >> 10) * HH + h;
    const int s0  = (t0 & 1023);

    // ---- GEMM q ----
    float acc[2][4][4];
    QKV_GEMM(acc, WQo);

    // stage q (bias, scale, tf32, permuted cols) into OUT_A
    {
        float b0r[4], b1r[4];
#pragma unroll
        for (int t = 0; t < 4; t++) {
            int e = wn * 32 + t * 8 + 2 * c;
            b0r[t] = bq[h * DHD + e];
            b1r[t] = bq[h * DHD + e + 1];
        }
#pragma unroll
        for (int m = 0; m < 2; m++) {
            int r = wm * 32 + m * 16 + g;
            float* p0 = &smf[OUTA + r * QSPW + wn * 32];
            float* p1 = &smf[OUTA + (r + 8) * QSPW + wn * 32];
#pragma unroll
            for (int t = 0; t < 4; t++) {
                p0[t * 8 + sl0]     = tf32rn((acc[m][t][0] + b0r[t]) * QSCALE);
                p0[t * 8 + sl0 + 2] = tf32rn((acc[m][t][1] + b1r[t]) * QSCALE);
                p1[t * 8 + sl0]     = tf32rn((acc[m][t][2] + b0r[t]) * QSCALE);
                p1[t * 8 + sl0 + 2] = tf32rn((acc[m][t][3] + b1r[t]) * QSCALE);
            }
        }
    }
    __syncthreads();   // B2: q fully staged in OUT_A

    // STG q (coalesced, from OUT_A) + GEMM k + stage k into OUT_B
#pragma unroll
    for (int p = 0; p < 8; p++) {
        int row = prow + p * 8;
        *(float4*)&g_q[((size_t)bh * SS + s0 + row) * DHD + pch * 4] =
            *(const float4*)&smf[OUTA + row * QSPW + pch * 4];
    }
    {
        float acck[2][4][4];
        QKV_GEMM(acck, WKo);
        float b0r[4], b1r[4];
#pragma unroll
        for (int t = 0; t < 4; t++) {
            int e = wn * 32 + t * 8 + 2 * c;
            b0r[t] = bk[h * DHD + e];
            b1r[t] = bk[h * DHD + e + 1];
        }
#pragma unroll
        for (int m = 0; m < 2; m++) {
            int r = wm * 32 + m * 16 + g;
            float* p0 = &smf[OUTB + r * QSPW + wn * 32];
            float* p1 = &smf[OUTB + (r + 8) * QSPW + wn * 32];
#pragma unroll
            for (int t = 0; t < 4; t++) {
                p0[t * 8 + sl0]     = tf32rn(acck[m][t][0] + b0r[t]);
                p0[t * 8 + sl0 + 2] = tf32rn(acck[m][t][1] + b1r[t]);
                p1[t * 8 + sl0]     = tf32rn(acck[m][t][2] + b0r[t]);
                p1[t * 8 + sl0 + 2] = tf32rn(acck[m][t][3] + b1r[t]);
            }
        }
    }
    __syncthreads();   // B3: k staged in OUT_B; all OUT_A reads done

    // STG k (from OUT_B) + GEMM v + stage vT into OUT_A (free since B3)
#pragma unroll
    for (int p = 0; p < 8; p++) {
        int row = prow + p * 8;
        *(float4*)&g_k[((size_t)bh * SS + s0 + row) * DHD + pch * 4] =
            *(const float4*)&smf[OUTB + row * QSPW + pch * 4];
    }
    {
        float accv[2][4][4];
        QKV_GEMM(accv, WVo);
        float b0r[4], b1r[4];
#pragma unroll
        for (int t = 0; t < 4; t++) {
            int e = wn * 32 + t * 8 + 2 * c;
            b0r[t] = bv[h * DHD + e];
            b1r[t] = bv[h * DHD + e + 1];
        }
#pragma unroll
        for (int m = 0; m < 2; m++) {
            int r    = wm * 32 + m * 16 + g;
            int ptk0 = r - g + slg;        // permuted token slot (row r)
            int ptk1 = ptk0 + 8;           // row r+8 (next octet, same slot)
#pragma unroll
            for (int t = 0; t < 4; t++) {
                int e = wn * 32 + t * 8 + 2 * c;
                smf[OUTA + e * QSPW + ptk0]       = tf32rn(accv[m][t][0] + b0r[t]);
                smf[OUTA + (e + 1) * QSPW + ptk0] = tf32rn(accv[m][t][1] + b1r[t]);
                smf[OUTA + e * QSPW + ptk1]       = tf32rn(accv[m][t][2] + b0r[t]);
                smf[OUTA + (e + 1) * QSPW + ptk1] = tf32rn(accv[m][t][3] + b1r[t]);
            }
        }
    }
    __syncthreads();   // B4: vT staged in OUT_A

    // STG vT: rows are e, columns are (permuted) tokens WITHIN the batch (s0)
#pragma unroll
    for (int p = 0; p < 8; p++) {
        int erow = prow + p * 8;
        *(float4*)&g_vT[((size_t)bh * DHD + erow) * SS + s0 + pch * 4] =
            *(const float4*)&smf[OUTA + erow * QSPW + pch * 4];
    }
}

// =====================================================================
// Kernel 2: tf32 mma.sync flash attention (byte-identical to R12 pass).
// =====================================================================
#define SPW 72
#define KF  0
#define V0F 4608
#define V1F 9216
#define PF  13824
#define LRF 18432
#define ATTN_SMEM ((18432 + 128) * 4)   // 74240 B

__global__ void __launch_bounds__(128, 3) attn_kernel(float* __restrict__ out)
{
    extern __shared__ float smf[];
    const uint32_t smb = smem_to_u32(smf);
    const int tid  = threadIdx.x;
    const int wid  = tid >> 5;
    const int lane = tid & 31;
    const int g    = lane >> 2;
    const int c    = lane & 3;
    const int wm   = wid >> 1;
    const int wn   = wid & 1;

    const int qt = blockIdx.x;
    const int bh = blockIdx.y;
    const int b  = bh >> 4, h = bh & 15;
    const int m0 = qt * 64;

    const float* qbase = g_q + (size_t)bh * SS * DHD;
    const float* kbase = g_k + (size_t)bh * SS * DHD;
    const float* vTb   = g_vT + (size_t)bh * DHD * SS;

    float* Psm  = smf + PF;
    float* lred = smf + LRF;

    const int prow = tid >> 4;
    const int pch  = tid & 15;
    const uint32_t kdst  = smb + (KF  + prow * SPW + pch * 4) * 4;
    const uint32_t v0dst = smb + (V0F + prow * SPW + pch * 4) * 4;
    const uint32_t v1dst = smb + (V1F + prow * SPW + pch * 4) * 4;
    const float* kgs = kbase + (size_t)prow * DHD + pch * 4;
    const float* vgs = vTb + (size_t)prow * SS + pch * 4;

#pragma unroll
    for (int p = 0; p < 8; p++) {
        cp16(kdst + p * (8 * SPW * 4), kgs + (size_t)p * 8 * DHD);
        cp16(v0dst + p * (8 * SPW * 4), vgs + (size_t)p * 8 * SS);
    }
    CP_COMMIT();

#pragma unroll
    for (int it = 0; it < 8; it++) {
        int idx = tid + it * 128;
        int row = idx >> 4;
        int ch  = idx & 15;
        *(float4*)&Psm[row * SPW + ch * 4] =
            *(const float4*)(qbase + (size_t)(m0 + row) * DHD + ch * 4);
    }
    __syncthreads();

    uint32_t qa[2][8][4];
#pragma unroll
    for (int m = 0; m < 2; m++) {
        int r = wm * 32 + m * 16 + g;
#pragma unroll
        for (int s = 0; s < 8; s++) {
            float2 lo = *(const float2*)&Psm[r * SPW + s * 8 + 2 * c];
            float2 hi = *(const float2*)&Psm[(r + 8) * SPW + s * 8 + 2 * c];
            qa[m][s][0] = __float_as_uint(lo.x);
            qa[m][s][1] = __float_as_uint(hi.x);
            qa[m][s][2] = __float_as_uint(lo.y);
            qa[m][s][3] = __float_as_uint(hi.y);
        }
    }

    float oacc[2][4][4];
#pragma unroll
    for (int m = 0; m < 2; m++)
#pragma unroll
        for (int t = 0; t < 4; t++)
#pragma unroll
            for (int q = 0; q < 4; q++) oacc[m][t][q] = 0.f;
    float lacc[2][2] = {{0.f, 0.f}, {0.f, 0.f}};

    const int sl0 = ((c & 1) << 2) | (c >> 1);

    for (int kt = 0; kt < 16; kt++) {
        CP_WAIT_ALL();
        __syncthreads();

        if (kt < 15) {
            uint32_t vd = (kt & 1) ? v0dst : v1dst;
            const float* vsrc = vgs + (size_t)(kt + 1) * 64;
#pragma unroll
            for (int p = 0; p < 8; p++)
                cp16(vd + p * (8 * SPW * 4), vsrc + (size_t)p * 8 * SS);
            CP_COMMIT();
        }

        const float* Kb = smf + KF;
        float sacc[2][4][4];
#pragma unroll
        for (int m = 0; m < 2; m++)
#pragma unroll
            for (int t = 0; t < 4; t++)
#pragma unroll
                for (int q = 0; q < 4; q++) sacc[m][t][q] = 0.f;
#pragma unroll
        for (int t = 0; t < 4; t++) {
            const float* bp = Kb + (wn * 32 + t * 8 + g) * SPW + 2 * c;
#pragma unroll
            for (int s = 0; s < 8; s++) {
                float2 b2 = *(const float2*)(bp + s * 8);
                uint32_t b0 = __float_as_uint(b2.x), b1 = __float_as_uint(b2.y);
                MMA_TF32(sacc[0][t], qa[0][s], b0, b1);
                MMA_TF32(sacc[1][t], qa[1][s], b0, b1);
            }
        }

#pragma unroll
        for (int m = 0; m < 2; m++) {
            int r = wm * 32 + m * 16 + g;
            float* p0 = Psm + r * SPW + wn * 32;
            float* p1 = Psm + (r + 8) * SPW + wn * 32;
#pragma unroll
            for (int t = 0; t < 4; t++) {
                float e0 = tf32rn(ex2f(sacc[m][t][0]));
                float e1 = tf32rn(ex2f(sacc[m][t][1]));
                float e2 = tf32rn(ex2f(sacc[m][t][2]));
                float e3 = tf32rn(ex2f(sacc[m][t][3]));
                lacc[m][0] += e0 + e1;
                lacc[m][1] += e2 + e3;
                p0[t * 8 + sl0]     = e0;
                p0[t * 8 + sl0 + 2] = e1;
                p1[t * 8 + sl0]     = e2;
                p1[t * 8 + sl0 + 2] = e3;
            }
        }
        __syncthreads();

        if (kt < 15) {
            const float* ksrc = kgs + (size_t)(kt + 1) * 64 * DHD;
#pragma unroll
            for (int p = 0; p < 8; p++)
                cp16(kdst + p * (8 * SPW * 4), ksrc + (size_t)p * 8 * DHD);
            CP_COMMIT();
        }

        const float* Vb = smf + ((kt & 1) ? V1F : V0F);
#pragma unroll
        for (int s = 0; s < 8; s++) {
            uint32_t pa[2][4];
#pragma unroll
            for (int m = 0; m < 2; m++) {
                int r = wm * 32 + m * 16 + g;
                float2 a0 = *(const float2*)(Psm + r * SPW + s * 8 + 2 * c);
                float2 a1 = *(const float2*)(Psm + (r + 8) * SPW + s * 8 + 2 * c);
                pa[m][0] = __float_as_uint(a0.x);
                pa[m][1] = __float_as_uint(a1.x);
                pa[m][2] = __float_as_uint(a0.y);
                pa[m][3] = __float_as_uint(a1.y);
            }
#pragma unroll
            for (int t = 0; t < 4; t++) {
                float2 b2 = *(const float2*)(Vb + (wn * 32 + t * 8 + g) * SPW + s * 8 + 2 * c);
                uint32_t b0 = __float_as_uint(b2.x), b1 = __float_as_uint(b2.y);
                MMA_TF32(oacc[0][t], pa[0], b0, b1);
                MMA_TF32(oacc[1][t], pa[1], b0, b1);
            }
        }
    }

#pragma unroll
    for (int m = 0; m < 2; m++)
#pragma unroll
        for (int hh = 0; hh < 2; hh++) {
            lacc[m][hh] += __shfl_xor_sync(0xffffffffu, lacc[m][hh], 1);
            lacc[m][hh] += __shfl_xor_sync(0xffffffffu, lacc[m][hh], 2);
        }
    if (c == 0) {
#pragma unroll
        for (int m = 0; m < 2; m++) {
            int r = wm * 32 + m * 16 + g;
            lred[r * 2 + wn]       = lacc[m][0];
            lred[(r + 8) * 2 + wn] = lacc[m][1];
        }
    }
    __syncthreads();

#pragma unroll
    for (int m = 0; m < 2; m++) {
        int r = wm * 32 + m * 16 + g;
        float inv0 = 1.f / (lred[r * 2] + lred[r * 2 + 1]);
        float inv1 = 1.f / (lred[(r + 8) * 2] + lred[(r + 8) * 2 + 1]);
        size_t o0 = (((size_t)b * SS + m0 + r) * HH + h) * DHD;
        size_t o1 = (((size_t)b * SS + m0 + r + 8) * HH + h) * DHD;
#pragma unroll
        for (int t = 0; t < 4; t++) {
            int col = wn * 32 + t * 8 + 2 * c;
            *(float2*)&out[o0 + col] =
                make_float2(oacc[m][t][0] * inv0, oacc[m][t][1] * inv0);
            *(float2*)&out[o1 + col] =
                make_float2(oacc[m][t][2] * inv1, oacc[m][t][3] * inv1);
        }
    }
}

// =====================================================================
extern "C" void kernel_launch(void* const* d_in, const int* in_sizes, int n_in,
                              void* d_out, int out_size)
{
    const float* x  = (const float*)d_in[0];
    const float* Wq = (const float*)d_in[1];
    const float* bq = (const float*)d_in[2];
    const float* Wk = (const float*)d_in[3];
    const float* bk = (const float*)d_in[4];
    const float* Wv = (const float*)d_in[5];
    const float* bv = (const float*)d_in[6];
    float* out = (float*)d_out;

    static bool attr_set = false;
    if (!attr_set) {
        cudaFuncSetAttribute(qkv_kernel,
                             cudaFuncAttributeMaxDynamicSharedMemorySize, QKV_SMEM);
        cudaFuncSetAttribute(attn_kernel,
                             cudaFuncAttributeMaxDynamicSharedMemorySize, ATTN_SMEM);
        attr_set = true;
    }

    qkv_kernel<<<dim3(128, 16), 128, QKV_SMEM>>>(x, Wq, bq, Wk, bk, Wv, bv);
    attn_kernel<<<dim3(16, 128), 128, ATTN_SMEM>>>(out);
}